// round 2
// baseline (speedup 1.0000x reference)
#include <cuda_runtime.h>
#include <cstdint>

// Hopf CPG oscillator step, B x 32 oscillators.
// out[:,0:32]  = 2*pi*v_a + coupling        (psi_dot)
// out[:,32:64] = r_d (passthrough of input cols 64:96)
// out[:,64:96] = c_a*(c_a*0.25*(b_a - r) - r_d)
//
// coupling_i = sum_j r_j * w_ij * sin(psi_j - psi_i - phi_ij)
// factored:  A_ij = w_a cos(phi_a), B_ij = w_a sin(phi_a)  (batch-independent)
//            t_j = r_j cos(psi_j), u_j = r_j sin(psi_j)
//            coupling_i = c_i*(A u - B t)_i - s_i*(A t + B u)_i
// packed f32x2: acc = sum_j (A,A)*(t,u) + (B,-B)*(u,t) = (Re,Im) = (At+Bu, Au-Bt)
//            coupling_i = c_i*Im - s_i*Re

#define NOSC 32

static constexpr float V_MAXc = 5.0f;
static constexpr float B_MAXc = 2.0f;
static constexpr float C_MAXc = 10.0f;
static constexpr float W_MAXc = 1.0f;
static constexpr float PHI_MAXc = 6.283185307179586f;
static constexpr float TWO_PIc = 6.283185307179586f;

__device__ __forceinline__ float sigmoidf_fast(float x) {
    return 1.0f / (1.0f + __expf(-x));
}

__device__ __forceinline__ unsigned long long pk2(float lo, float hi) {
    unsigned long long r;
    asm("mov.b64 %0, {%1, %2};" : "=l"(r) : "f"(lo), "f"(hi));
    return r;
}
__device__ __forceinline__ unsigned long long fma2(unsigned long long a,
                                                   unsigned long long b,
                                                   unsigned long long c) {
    unsigned long long d;
    asm("fma.rn.f32x2 %0, %1, %2, %3;" : "=l"(d) : "l"(a), "l"(b), "l"(c));
    return d;
}
__device__ __forceinline__ unsigned long long add2(unsigned long long a,
                                                   unsigned long long b) {
    unsigned long long d;
    asm("add.rn.f32x2 %0, %1, %2;" : "=l"(d) : "l"(a), "l"(b));
    return d;
}
__device__ __forceinline__ void upk2(unsigned long long v, float& lo, float& hi) {
    asm("mov.b64 {%0, %1}, %2;" : "=f"(lo), "=f"(hi) : "l"(v));
}

__global__ __launch_bounds__(128, 3)
void hopf_step_kernel(const float* __restrict__ cpg,
                      const float* __restrict__ v,
                      const float* __restrict__ b,
                      const float* __restrict__ c,
                      const float* __restrict__ w,
                      const float* __restrict__ phi,
                      float* __restrict__ out,
                      int B)
{
    // Transposed so the per-thread register load below is conflict-free:
    // sAT[j*32 + i] = A_ij
    __shared__ float sAT[NOSC * NOSC];
    __shared__ float sBT[NOSC * NOSC];
    __shared__ float sva[NOSC], sba[NOSC], sca[NOSC];
    __shared__ float4 zbuf[4][2][NOSC];   // [warp][parity][j] = (t,u,u,t)

    const int tid = threadIdx.x;

    // ---- batch-independent parameter preprocessing (per block, cheap) ----
    if (tid < NOSC) {
        sva[tid] = V_MAXc * sigmoidf_fast(v[tid]);
        sba[tid] = B_MAXc * sigmoidf_fast(b[tid]);
        sca[tid] = C_MAXc * sigmoidf_fast(c[tid]);
    }
    // _zero_diag mapping: flat k (=i*32+j) of the 32x32 result corresponds to
    // flat index k of a (31,33) matrix whose col 0 is zeros; so k%33==0 -> 0,
    // otherwise param[(k/33)*32 + (k%33 - 1)]. k=1023 also maps to k%33==0.
    for (int k = tid; k < NOSC * NOSC; k += 128) {
        const int i = k >> 5;
        const int j = k & 31;
        float A = 0.0f, Bm = 0.0f;
        const int cpos = k % 33;
        if (cpos != 0) {
            const int pidx = (k / 33) * 32 + (cpos - 1);
            const float wa = W_MAXc * sigmoidf_fast(w[pidx]);
            const float pa = PHI_MAXc * sigmoidf_fast(phi[pidx]);
            float sp, cp;
            __sincosf(pa, &sp, &cp);
            A  = wa * cp;
            Bm = wa * sp;
        }
        sAT[j * 32 + i] = A;
        sBT[j * 32 + i] = Bm;
    }
    __syncthreads();

    const int lane = tid & 31;   // oscillator index i owned by this thread
    const int wid  = tid >> 5;

    // Matrix row i of A / B lives in registers, packed for f32x2.
    unsigned long long Ap[NOSC], Bp[NOSC];
#pragma unroll
    for (int j = 0; j < NOSC; j++) {
        const float a  = sAT[j * 32 + lane];
        const float bb = sBT[j * 32 + lane];
        Ap[j] = pk2(a, a);
        Bp[j] = pk2(bb, -bb);
    }
    const float va = sva[lane];
    const float ba = sba[lane];
    const float ca = sca[lane];

    const uint32_t zb0 = (uint32_t)__cvta_generic_to_shared(&zbuf[wid][0][0]);
    const uint32_t zb1 = (uint32_t)__cvta_generic_to_shared(&zbuf[wid][1][0]);

    const int gw     = blockIdx.x * 4 + wid;     // global warp id
    const int stride = gridDim.x * 4;            // total warps

    long row = gw;
    float psi = 0.0f, r = 0.0f, rd = 0.0f;
    if (row < B) {
        const float* p = cpg + row * 96 + lane;
        psi = p[0];
        r   = p[32];
        rd  = p[64];
    }

    int parity = 0;
    while (row < B) {
        float s, ct;
        __sincosf(psi, &s, &ct);
        const float t = r * ct;
        const float u = r * s;
        zbuf[wid][parity][lane] = make_float4(t, u, u, t);

        const float r_cur  = r;
        const float rd_cur = rd;
        const float s_cur  = s;
        const float c_cur  = ct;

        __syncwarp();

        // prefetch next row while the FMA loop runs
        const long nrow = row + stride;
        if (nrow < B) {
            const float* p = cpg + nrow * 96 + lane;
            psi = p[0];
            r   = p[32];
            rd  = p[64];
        }

        unsigned long long accA = 0ULL;   // (0.f, 0.f)
        unsigned long long accB = 0ULL;
        const uint32_t zaddr = parity ? zb1 : zb0;
#pragma unroll
        for (int j = 0; j < NOSC; j++) {
            unsigned long long zt, zu;
            asm volatile("ld.shared.v2.b64 {%0, %1}, [%2];"
                         : "=l"(zt), "=l"(zu)
                         : "r"(zaddr + j * 16));
            accA = fma2(Ap[j], zt, accA);
            accB = fma2(Bp[j], zu, accB);
        }
        const unsigned long long acc = add2(accA, accB);
        float Re, Im;
        upk2(acc, Re, Im);

        const float coupling = c_cur * Im - s_cur * Re;
        const float psid = fmaf(TWO_PIc, va, coupling);
        const float rdd  = ca * fmaf(0.25f * ca, ba - r_cur, -rd_cur);

        float* o = out + row * 96 + lane;
        o[0]  = psid;
        o[32] = rd_cur;
        o[64] = rdd;

        row = nrow;
        parity ^= 1;
    }
}

extern "C" void kernel_launch(void* const* d_in, const int* in_sizes, int n_in,
                              void* d_out, int out_size) {
    const float* cpg = (const float*)d_in[0];
    const float* v   = (const float*)d_in[1];
    const float* b   = (const float*)d_in[2];
    const float* c   = (const float*)d_in[3];
    const float* w   = (const float*)d_in[4];
    const float* phi = (const float*)d_in[5];
    float* out = (float*)d_out;

    const int B = in_sizes[0] / 96;

    // 4 warps/block, ~32 rows per warp to amortize the 128-reg matrix setup.
    int blocks = (B + 127) / 128;
    if (blocks < 1) blocks = 1;
    if (blocks > 2048) blocks = 2048;

    hopf_step_kernel<<<blocks, 128>>>(cpg, v, b, c, w, phi, out, B);
}

// round 3
// speedup vs baseline: 1.2797x; 1.2797x over previous
#include <cuda_runtime.h>
#include <cstdint>

// Hopf CPG oscillator step, B x 32 oscillators.
// coupling_i = sum_j r_j * w_ij * sin(psi_j - psi_i - phi_ij)
// Factored (batch-independent A=w cos(phi), B=w sin(phi); t=r cos(psi), u=r sin(psi)):
//   coupling_i = cos(psi_i)*(A u - B t)_i - sin(psi_i)*(A t + B u)_i
// Packed trick (ONE 64-bit weight reg per j):  W_j = (a_j, b_j)
//   P = sum_j W_j * (t_j, u_j)  = (Σ a t, Σ b u)  ->  Re = P.lo + P.hi = (A t + B u)
//   Q = sum_j W_j * (u_j, t_j)  = (Σ a u, Σ b t)  ->  Im = Q.lo - Q.hi = (A u - B t)

#define NOSC 32

static constexpr float V_MAXc = 5.0f;
static constexpr float B_MAXc = 2.0f;
static constexpr float C_MAXc = 10.0f;
static constexpr float W_MAXc = 1.0f;
static constexpr float PHI_MAXc = 6.283185307179586f;
static constexpr float TWO_PIc = 6.283185307179586f;

__device__ __forceinline__ float sigmoidf_fast(float x) {
    return 1.0f / (1.0f + __expf(-x));
}

__device__ __forceinline__ unsigned long long fma2(unsigned long long a,
                                                   unsigned long long b,
                                                   unsigned long long c) {
    unsigned long long d;
    asm("fma.rn.f32x2 %0, %1, %2, %3;" : "=l"(d) : "l"(a), "l"(b), "l"(c));
    return d;
}
__device__ __forceinline__ void upk2(unsigned long long v, float& lo, float& hi) {
    asm("mov.b64 {%0, %1}, %2;" : "=f"(lo), "=f"(hi) : "l"(v));
}

__global__ __launch_bounds__(128, 4)
void hopf_step_kernel(const float* __restrict__ cpg,
                      const float* __restrict__ v,
                      const float* __restrict__ b,
                      const float* __restrict__ c,
                      const float* __restrict__ w,
                      const float* __restrict__ phi,
                      float* __restrict__ out,
                      int B)
{
    // sW[j*32 + i] = (A_ij, B_ij)   -- transposed so per-lane load is conflict-free
    __shared__ float2 sW[NOSC * NOSC];
    __shared__ float sva[NOSC], sba[NOSC], sca[NOSC];
    // [warp][parity][rowpair][j] = (t,u,u,t)
    __shared__ float4 zbuf[4][2][2][NOSC];

    const int tid = threadIdx.x;

    // ---- batch-independent parameter preprocessing ----
    if (tid < NOSC) {
        sva[tid] = V_MAXc * sigmoidf_fast(v[tid]);
        sba[tid] = B_MAXc * sigmoidf_fast(b[tid]);
        sca[tid] = C_MAXc * sigmoidf_fast(c[tid]);
    }
    // _zero_diag: flat k of the 32x32 result maps to a (31,33) matrix with a
    // zero first column: k%33==0 -> 0, else param[(k/33)*32 + (k%33 - 1)].
    for (int k = tid; k < NOSC * NOSC; k += 128) {
        const int i = k >> 5;
        const int j = k & 31;
        float A = 0.0f, Bm = 0.0f;
        const int cpos = k % 33;
        if (cpos != 0) {
            const int pidx = (k / 33) * 32 + (cpos - 1);
            const float wa = W_MAXc * sigmoidf_fast(w[pidx]);
            const float pa = PHI_MAXc * sigmoidf_fast(phi[pidx]);
            float sp, cp;
            __sincosf(pa, &sp, &cp);
            A  = wa * cp;
            Bm = wa * sp;
        }
        sW[j * 32 + i] = make_float2(A, Bm);
    }
    __syncthreads();

    const int lane = tid & 31;   // oscillator index i owned by this thread
    const int wid  = tid >> 5;

    // One packed 64-bit weight per j: W_j = (A_ij, B_ij). 64 registers total.
    unsigned long long W[NOSC];
#pragma unroll
    for (int j = 0; j < NOSC; j++) {
        W[j] = *reinterpret_cast<const unsigned long long*>(&sW[j * 32 + lane]);
    }
    const float va = sva[lane];
    const float ba = sba[lane];
    const float ca = sca[lane];

    const uint32_t zbase =
        (uint32_t)__cvta_generic_to_shared(&zbuf[wid][0][0][0]);

    const int gw     = blockIdx.x * 4 + wid;     // global warp id
    const int stride = gridDim.x * 4;            // total warps
    const int step   = 2 * stride;               // rows per sweep (2 rows/warp)

    int row0 = 2 * gw;
    float psi0 = 0.f, r0 = 0.f, rd0 = 0.f;
    float psi1 = 0.f, r1 = 0.f, rd1 = 0.f;
    if (row0 < B) {
        const float* p = cpg + (long)row0 * 96 + lane;
        psi0 = p[0];  r0 = p[32];  rd0 = p[64];
        if (row0 + 1 < B) {
            psi1 = p[96]; r1 = p[128]; rd1 = p[160];
        }
    }

    int parity = 0;
    while (row0 < B) {
        const int row1 = row0 + 1;

        float s0, c0, s1, c1;
        __sincosf(psi0, &s0, &c0);
        __sincosf(psi1, &s1, &c1);
        const float t0 = r0 * c0, u0 = r0 * s0;
        const float t1 = r1 * c1, u1 = r1 * s1;
        zbuf[wid][parity][0][lane] = make_float4(t0, u0, u0, t0);
        zbuf[wid][parity][1][lane] = make_float4(t1, u1, u1, t1);

        const float rA = r0,  rdA = rd0, sA = s0, cA = c0;
        const float rB = r1,  rdB = rd1, sB = s1, cB = c1;

        __syncwarp();

        // prefetch next row pair while the FMA loop runs
        const int nrow = row0 + step;
        if (nrow < B) {
            const float* p = cpg + (long)nrow * 96 + lane;
            psi0 = p[0];  r0 = p[32];  rd0 = p[64];
            if (nrow + 1 < B) {
                psi1 = p[96]; r1 = p[128]; rd1 = p[160];
            }
        }

        unsigned long long P0 = 0ULL, Q0 = 0ULL, P1 = 0ULL, Q1 = 0ULL;
        const uint32_t z0 = zbase + (uint32_t)parity * 1024u;
        const uint32_t z1 = z0 + 512u;
#pragma unroll
        for (int j = 0; j < NOSC; j++) {
            unsigned long long zt0, zu0, zt1, zu1;
            asm volatile("ld.shared.v2.b64 {%0, %1}, [%2];"
                         : "=l"(zt0), "=l"(zu0) : "r"(z0 + j * 16));
            asm volatile("ld.shared.v2.b64 {%0, %1}, [%2];"
                         : "=l"(zt1), "=l"(zu1) : "r"(z1 + j * 16));
            P0 = fma2(W[j], zt0, P0);
            Q0 = fma2(W[j], zu0, Q0);
            P1 = fma2(W[j], zt1, P1);
            Q1 = fma2(W[j], zu1, Q1);
        }

        float at0, bu0, au0, bt0, at1, bu1, au1, bt1;
        upk2(P0, at0, bu0);  upk2(Q0, au0, bt0);
        upk2(P1, at1, bu1);  upk2(Q1, au1, bt1);

        {   // row0 epilogue
            const float Re = at0 + bu0;
            const float Im = au0 - bt0;
            const float coupling = cA * Im - sA * Re;
            const float psid = fmaf(TWO_PIc, va, coupling);
            const float rdd  = ca * fmaf(0.25f * ca, ba - rA, -rdA);
            float* o = out + (long)row0 * 96 + lane;
            o[0] = psid;  o[32] = rdA;  o[64] = rdd;
        }
        if (row1 < B) {   // row1 epilogue
            const float Re = at1 + bu1;
            const float Im = au1 - bt1;
            const float coupling = cB * Im - sB * Re;
            const float psid = fmaf(TWO_PIc, va, coupling);
            const float rdd  = ca * fmaf(0.25f * ca, ba - rB, -rdB);
            float* o = out + (long)row1 * 96 + lane;
            o[0] = psid;  o[32] = rdB;  o[64] = rdd;
        }

        row0 = nrow;
        parity ^= 1;
    }
}

extern "C" void kernel_launch(void* const* d_in, const int* in_sizes, int n_in,
                              void* d_out, int out_size) {
    const float* cpg = (const float*)d_in[0];
    const float* v   = (const float*)d_in[1];
    const float* b   = (const float*)d_in[2];
    const float* c   = (const float*)d_in[3];
    const float* w   = (const float*)d_in[4];
    const float* phi = (const float*)d_in[5];
    float* out = (float*)d_out;

    const int B = in_sizes[0] / 96;

    // 148 SMs x 4 CTAs resident -> persistent-style stride loop, ~2 waves max.
    int blocks = 592;
    int need = (B + 255) / 256;   // each block covers >= 8 rows/iter (4 warps x 2)
    if (need < blocks) blocks = need;
    if (blocks < 1) blocks = 1;

    hopf_step_kernel<<<blocks, 128>>>(cpg, v, b, c, w, phi, out, B);
}

// round 4
// speedup vs baseline: 1.3816x; 1.0796x over previous
#include <cuda_runtime.h>
#include <cstdint>

// Hopf CPG oscillator step, B x 32 oscillators.
// coupling_i = sum_j r_j * w_ij * sin(psi_j - psi_i - phi_ij)
// Factored (batch-independent A=w cos(phi), B=w sin(phi); t=r cos(psi), u=r sin(psi)):
//   coupling_i = cos(psi_i)*(A u - B t)_i - sin(psi_i)*(A t + B u)_i
// Packed trick (ONE 64-bit weight reg per j):  W_j = (a_j, b_j)
//   P = sum_j W_j * (t_j, u_j)  = (Σ a t, Σ b u)  ->  Re = P.lo + P.hi
//   Q = sum_j W_j * (u_j, t_j)  = (Σ a u, Σ b t)  ->  Im = Q.lo - Q.hi

#define NOSC 32

static constexpr float V_MAXc = 5.0f;
static constexpr float B_MAXc = 2.0f;
static constexpr float C_MAXc = 10.0f;
static constexpr float W_MAXc = 1.0f;
static constexpr float PHI_MAXc = 6.283185307179586f;
static constexpr float TWO_PIc = 6.283185307179586f;

__device__ __forceinline__ float sigmoidf_fast(float x) {
    return 1.0f / (1.0f + __expf(-x));
}

__device__ __forceinline__ unsigned long long fma2(unsigned long long a,
                                                   unsigned long long b,
                                                   unsigned long long c) {
    unsigned long long d;
    asm("fma.rn.f32x2 %0, %1, %2, %3;" : "=l"(d) : "l"(a), "l"(b), "l"(c));
    return d;
}
__device__ __forceinline__ void upk2(unsigned long long v, float& lo, float& hi) {
    asm("mov.b64 {%0, %1}, %2;" : "=f"(lo), "=f"(hi) : "l"(v));
}

__global__ __launch_bounds__(128, 4)
void hopf_step_kernel(const float* __restrict__ cpg,
                      const float* __restrict__ v,
                      const float* __restrict__ b,
                      const float* __restrict__ c,
                      const float* __restrict__ w,
                      const float* __restrict__ phi,
                      float* __restrict__ out,
                      int B)
{
    // sW[j*32 + i] = (A_ij, B_ij)   -- transposed so per-lane load is conflict-free
    __shared__ float2 sW[NOSC * NOSC];
    __shared__ float sva[NOSC], sba[NOSC], sca[NOSC];
    // [warp][parity][rowpair][j] = (t,u,u,t)
    __shared__ float4 zbuf[4][2][2][NOSC];

    const int tid = threadIdx.x;

    // ---- batch-independent parameter preprocessing ----
    if (tid < NOSC) {
        sva[tid] = V_MAXc * sigmoidf_fast(v[tid]);
        sba[tid] = B_MAXc * sigmoidf_fast(b[tid]);
        sca[tid] = C_MAXc * sigmoidf_fast(c[tid]);
    }
    // _zero_diag: flat k of the 32x32 result maps to a (31,33) matrix with a
    // zero first column: k%33==0 -> 0, else param[(k/33)*32 + (k%33 - 1)].
    for (int k = tid; k < NOSC * NOSC; k += 128) {
        const int i = k >> 5;
        const int j = k & 31;
        float A = 0.0f, Bm = 0.0f;
        const int cpos = k % 33;
        if (cpos != 0) {
            const int pidx = (k / 33) * 32 + (cpos - 1);
            const float wa = W_MAXc * sigmoidf_fast(w[pidx]);
            const float pa = PHI_MAXc * sigmoidf_fast(phi[pidx]);
            float sp, cp;
            __sincosf(pa, &sp, &cp);
            A  = wa * cp;
            Bm = wa * sp;
        }
        sW[j * 32 + i] = make_float2(A, Bm);
    }
    __syncthreads();

    const int lane = tid & 31;   // oscillator index i owned by this thread
    const int wid  = tid >> 5;

    // One packed 64-bit weight per j: W_j = (A_ij, B_ij). 64 registers total.
    unsigned long long W[NOSC];
#pragma unroll
    for (int j = 0; j < NOSC; j++) {
        W[j] = *reinterpret_cast<const unsigned long long*>(&sW[j * 32 + lane]);
    }
    const float va = sva[lane];
    const float ba = sba[lane];
    const float ca = sca[lane];

    const uint32_t zbase =
        (uint32_t)__cvta_generic_to_shared(&zbuf[wid][0][0][0]);

    const int gw     = blockIdx.x * 4 + wid;     // global warp id
    const int stride = gridDim.x * 4;            // total warps
    const int step   = 2 * stride;               // rows per sweep (2 rows/warp)
    const long pstep = (long)step * 96;

    int row0 = 2 * gw;
    const float* pin  = cpg + (long)row0 * 96 + lane;
    float*       pout = out + (long)row0 * 96 + lane;

    float psi0 = 0.f, r0 = 0.f, rd0 = 0.f;
    float psi1 = 0.f, r1 = 0.f, rd1 = 0.f;
    if (row0 < B) {
        psi0 = pin[0];  r0 = pin[32];  rd0 = pin[64];
        if (row0 + 1 < B) {
            psi1 = pin[96]; r1 = pin[128]; rd1 = pin[160];
        }
    }

    int parity = 0;
    while (row0 < B) {
        const int row1 = row0 + 1;

        float s0, c0, s1, c1;
        __sincosf(psi0, &s0, &c0);
        __sincosf(psi1, &s1, &c1);
        const float t0 = r0 * c0, u0 = r0 * s0;
        const float t1 = r1 * c1, u1 = r1 * s1;
        zbuf[wid][parity][0][lane] = make_float4(t0, u0, u0, t0);
        zbuf[wid][parity][1][lane] = make_float4(t1, u1, u1, t1);

        const float rA = r0,  rdA = rd0, sA = s0, cA = c0;
        const float rB = r1,  rdB = rd1, sB = s1, cB = c1;

        __syncwarp();

        // prefetch next row pair while the FMA loop runs
        const int nrow = row0 + step;
        pin += pstep;
        if (nrow < B) {
            psi0 = pin[0];  r0 = pin[32];  rd0 = pin[64];
            if (nrow + 1 < B) {
                psi1 = pin[96]; r1 = pin[128]; rd1 = pin[160];
            }
        }

        unsigned long long P0 = 0ULL, Q0 = 0ULL, P1 = 0ULL, Q1 = 0ULL;
        const uint32_t z0 = zbase + (uint32_t)parity * 1024u;
        const uint32_t z1 = z0 + 512u;
#pragma unroll
        for (int j = 0; j < NOSC; j++) {
            unsigned long long zt0, zu0, zt1, zu1;
            asm volatile("ld.shared.v2.b64 {%0, %1}, [%2];"
                         : "=l"(zt0), "=l"(zu0) : "r"(z0 + j * 16));
            asm volatile("ld.shared.v2.b64 {%0, %1}, [%2];"
                         : "=l"(zt1), "=l"(zu1) : "r"(z1 + j * 16));
            P0 = fma2(W[j], zt0, P0);
            Q0 = fma2(W[j], zu0, Q0);
            P1 = fma2(W[j], zt1, P1);
            Q1 = fma2(W[j], zu1, Q1);
        }

        float at0, bu0, au0, bt0, at1, bu1, au1, bt1;
        upk2(P0, at0, bu0);  upk2(Q0, au0, bt0);
        upk2(P1, at1, bu1);  upk2(Q1, au1, bt1);

        {   // row0 epilogue
            const float Re = at0 + bu0;
            const float Im = au0 - bt0;
            const float coupling = cA * Im - sA * Re;
            const float psid = fmaf(TWO_PIc, va, coupling);
            const float rdd  = ca * fmaf(0.25f * ca, ba - rA, -rdA);
            pout[0] = psid;  pout[32] = rdA;  pout[64] = rdd;
        }
        if (row1 < B) {   // row1 epilogue
            const float Re = at1 + bu1;
            const float Im = au1 - bt1;
            const float coupling = cB * Im - sB * Re;
            const float psid = fmaf(TWO_PIc, va, coupling);
            const float rdd  = ca * fmaf(0.25f * ca, ba - rB, -rdB);
            pout[96] = psid;  pout[128] = rdB;  pout[160] = rdd;
        }

        pout += pstep;
        row0 = nrow;
        parity ^= 1;
    }
}

extern "C" void kernel_launch(void* const* d_in, const int* in_sizes, int n_in,
                              void* d_out, int out_size) {
    const float* cpg = (const float*)d_in[0];
    const float* v   = (const float*)d_in[1];
    const float* b   = (const float*)d_in[2];
    const float* c   = (const float*)d_in[3];
    const float* w   = (const float*)d_in[4];
    const float* phi = (const float*)d_in[5];
    float* out = (float*)d_out;

    const int B = in_sizes[0] / 96;

    // Full residency: 4 CTAs/SM x 148 SMs. Each block still needs >=1 row pair.
    int blocks = 592;
    int maxb = (B + 7) / 8;      // 4 warps x 2 rows minimum useful work
    if (blocks > maxb) blocks = maxb;
    if (blocks < 1) blocks = 1;

    hopf_step_kernel<<<blocks, 128>>>(cpg, v, b, c, w, phi, out, B);
}